// round 13
// baseline (speedup 1.0000x reference)
#include <cuda_runtime.h>
#include <stdint.h>

// TwoHotEmbedding: out[b,s,:] = W[i1[b,s]] + (i1!=i2 ? W[i2[b,s]] : 0)
// i1,i2 [8,4096] int32; W [50257,512] f32; out [8,4096,512] f32.
//
// FINAL (R2 configuration — best measured kernel time, 22.8us @ 4.55TB/s):
//   - warp-per-token: lane owns float4 chunks {lane, lane+32, lane+64, lane+96}
//   - 8 independent __ldg float4 gathers, front-batched (MLP=8)
//   - branch-free: second row blended with warp-uniform 0/1 FMA multiplier
//   - __stcs (evict_first) streaming stores
//   - 256 threads/block, 4096 CTAs, regs=32, occ ~78%
//
// Conclusions from R1-R12 on sm_103a:
//   * traffic floor ~104MB/replay: 64MB compulsory writes + ~38MB L2
//     capacity-overflow reads (75MB touched-W + 64MB output > 126MB L2)
//   * 4.6-4.7 TB/s is the mixed random-read/stream-write HBM ceiling here
//   * L2 eviction-policy hints (all legal encodings) move <=1us
//   * v8.b32 accesses and persistent grids regress via register pressure

static constexpr int NTOK = 8 * 4096;   // 32768 tokens
static constexpr int CHUNKS = 128;      // float4 per row

__global__ void __launch_bounds__(256)
twohot_kernel(const int* __restrict__ i1,
              const int* __restrict__ i2,
              const float4* __restrict__ W,
              float4* __restrict__ out)
{
    int warp = blockIdx.x * (blockDim.x >> 5) + (threadIdx.x >> 5);
    int lane = threadIdx.x & 31;
    if (warp >= NTOK) return;

    int a = __ldg(i1 + warp);   // warp-uniform broadcast
    int b = __ldg(i2 + warp);

    const float4* ra = W + (long long)a * CHUNKS + lane;
    const float4* rb = W + (long long)b * CHUNKS + lane;
    float4* o = out + (long long)warp * CHUNKS + lane;

    // 8 independent gathers, front-batched (MLP=8).
    float4 a0 = __ldg(ra + 0);
    float4 a1 = __ldg(ra + 32);
    float4 a2 = __ldg(ra + 64);
    float4 a3 = __ldg(ra + 96);
    float4 b0 = __ldg(rb + 0);
    float4 b1 = __ldg(rb + 32);
    float4 b2 = __ldg(rb + 64);
    float4 b3 = __ldg(rb + 96);

    float m = (a != b) ? 1.0f : 0.0f;   // warp-uniform

    a0.x = fmaf(m, b0.x, a0.x); a0.y = fmaf(m, b0.y, a0.y);
    a0.z = fmaf(m, b0.z, a0.z); a0.w = fmaf(m, b0.w, a0.w);
    a1.x = fmaf(m, b1.x, a1.x); a1.y = fmaf(m, b1.y, a1.y);
    a1.z = fmaf(m, b1.z, a1.z); a1.w = fmaf(m, b1.w, a1.w);
    a2.x = fmaf(m, b2.x, a2.x); a2.y = fmaf(m, b2.y, a2.y);
    a2.z = fmaf(m, b2.z, a2.z); a2.w = fmaf(m, b2.w, a2.w);
    a3.x = fmaf(m, b3.x, a3.x); a3.y = fmaf(m, b3.y, a3.y);
    a3.z = fmaf(m, b3.z, a3.z); a3.w = fmaf(m, b3.w, a3.w);

    __stcs(o + 0,  a0);
    __stcs(o + 32, a1);
    __stcs(o + 64, a2);
    __stcs(o + 96, a3);
}

extern "C" void kernel_launch(void* const* d_in, const int* in_sizes, int n_in,
                              void* d_out, int out_size)
{
    const int*    i1 = (const int*)d_in[0];
    const int*    i2 = (const int*)d_in[1];
    const float4* W  = (const float4*)d_in[2];
    float4*       out = (float4*)d_out;

    const int threads = 256;          // 8 warps = 8 tokens per block
    const int blocks = NTOK / 8;      // 4096 blocks
    twohot_kernel<<<blocks, threads>>>(i1, i2, W, out);
}

// round 14
// speedup vs baseline: 1.0089x; 1.0089x over previous
#include <cuda_runtime.h>
#include <stdint.h>

// TwoHotEmbedding: out[b,s,:] = W[i1[b,s]] + (i1!=i2 ? W[i2[b,s]] : 0)
// i1,i2 [8,4096] int32; W [50257,512] f32; out [8,4096,512] f32.
//
// FINAL — best measured configuration (R12: bench 25.056us, kernel 22.976us):
//   - warp-per-token: lane owns float4 chunks {lane, lane+32, lane+64, lane+96}
//   - 8 independent __ldg float4 gathers, front-batched (MLP=8)
//   - branch-free: second row blended with warp-uniform 0/1 FMA multiplier
//   - stores: fractional evict_last(0.25)/evict_first policy via
//     st.global.L2::cache_hint (never measured worse than .cs; best bench)
//   - 256 threads/block, 4096 CTAs, regs=32, occ ~78%
//
// Closed conclusions from R1-R13 on sm_103a:
//   * traffic floor ~104MB/replay: 64MB compulsory writes + ~38MB L2
//     capacity-overflow reads (75MB touched-W + 64MB output > 126MB L2)
//   * 4.6-4.7 TB/s is the mixed random-read/stream-write HBM ceiling here
//   * L2 eviction-policy hints (all legal encodings) move <=1us
//   * v8.b32 accesses, persistent grids, write-through all regress

static constexpr int NTOK = 8 * 4096;   // 32768 tokens
static constexpr int CHUNKS = 128;      // float4 per row

__device__ __forceinline__ void stg_pol(float4* p, const float4 v, uint64_t pol)
{
    asm volatile("st.global.L2::cache_hint.v4.f32 [%0], {%1,%2,%3,%4}, %5;"
                 :: "l"(p), "f"(v.x), "f"(v.y), "f"(v.z), "f"(v.w), "l"(pol)
                 : "memory");
}

__global__ void __launch_bounds__(256)
twohot_kernel(const int* __restrict__ i1,
              const int* __restrict__ i2,
              const float4* __restrict__ W,
              float4* __restrict__ out)
{
    int warp = blockIdx.x * (blockDim.x >> 5) + (threadIdx.x >> 5);
    int lane = threadIdx.x & 31;
    if (warp >= NTOK) return;

    uint64_t pol;
    asm("createpolicy.fractional.L2::evict_last.L2::evict_first.b64 %0, 0.25;"
        : "=l"(pol));

    int a = __ldg(i1 + warp);   // warp-uniform broadcast
    int b = __ldg(i2 + warp);

    const float4* ra = W + (long long)a * CHUNKS + lane;
    const float4* rb = W + (long long)b * CHUNKS + lane;
    float4* o = out + (long long)warp * CHUNKS + lane;

    // 8 independent gathers, front-batched (MLP=8), normal L2 allocation.
    float4 a0 = __ldg(ra + 0);
    float4 a1 = __ldg(ra + 32);
    float4 a2 = __ldg(ra + 64);
    float4 a3 = __ldg(ra + 96);
    float4 b0 = __ldg(rb + 0);
    float4 b1 = __ldg(rb + 32);
    float4 b2 = __ldg(rb + 64);
    float4 b3 = __ldg(rb + 96);

    float m = (a != b) ? 1.0f : 0.0f;   // warp-uniform

    a0.x = fmaf(m, b0.x, a0.x); a0.y = fmaf(m, b0.y, a0.y);
    a0.z = fmaf(m, b0.z, a0.z); a0.w = fmaf(m, b0.w, a0.w);
    a1.x = fmaf(m, b1.x, a1.x); a1.y = fmaf(m, b1.y, a1.y);
    a1.z = fmaf(m, b1.z, a1.z); a1.w = fmaf(m, b1.w, a1.w);
    a2.x = fmaf(m, b2.x, a2.x); a2.y = fmaf(m, b2.y, a2.y);
    a2.z = fmaf(m, b2.z, a2.z); a2.w = fmaf(m, b2.w, a2.w);
    a3.x = fmaf(m, b3.x, a3.x); a3.y = fmaf(m, b3.y, a3.y);
    a3.z = fmaf(m, b3.z, a3.z); a3.w = fmaf(m, b3.w, a3.w);

    stg_pol(o + 0,  a0, pol);
    stg_pol(o + 32, a1, pol);
    stg_pol(o + 64, a2, pol);
    stg_pol(o + 96, a3, pol);
}

extern "C" void kernel_launch(void* const* d_in, const int* in_sizes, int n_in,
                              void* d_out, int out_size)
{
    const int*    i1 = (const int*)d_in[0];
    const int*    i2 = (const int*)d_in[1];
    const float4* W  = (const float4*)d_in[2];
    float4*       out = (float4*)d_out;

    const int threads = 256;          // 8 warps = 8 tokens per block
    const int blocks = NTOK / 8;      // 4096 blocks
    twohot_kernel<<<blocks, threads>>>(i1, i2, W, out);
}